// round 7
// baseline (speedup 1.0000x reference)
#include <cuda_runtime.h>

// Problem constants
#define Bv 64
#define Cv 256
#define Nv 307
#define Tv 12
#define NT (Nv * Tv)     // 3684
#define NT4 (NT / 4)     // 921 float4 per (b,c) row

// Scratch (device globals: allocation-free rule)
__device__ float g_k[Bv * Cv * Tv];             // pooled k: [B, C, T]
__device__ float g_attT[(size_t)Bv * Cv * Cv];  // softmax(att) TRANSPOSED: [b][d][c]

// ---- f32x2 packed-FMA helpers (Blackwell FFMA2; PTX-only) ----
__device__ __forceinline__ void fma_f32x2(unsigned long long& d,
                                          unsigned long long a,
                                          unsigned long long b) {
    asm("fma.rn.f32x2 %0, %1, %2, %0;" : "+l"(d) : "l"(a), "l"(b));
}
__device__ __forceinline__ void unpack_f32x2(unsigned long long p, float& lo, float& hi) {
    unsigned int l, h;
    asm("mov.b64 {%0, %1}, %2;" : "=r"(l), "=r"(h) : "l"(p));
    lo = __uint_as_float(l);
    hi = __uint_as_float(h);
}

// ---------------------------------------------------------------------------
// Stage 1 (v2): k[b,c,t] = sum_i alpha[i] * x[b,c,i,t]
// 4 rows per block, 384 threads (96/row). float4 loads; 96 % 3 == 0 keeps each
// thread's t-phase (f%3) constant, so a float4 accumulator works directly.
// ---------------------------------------------------------------------------
__global__ __launch_bounds__(384) void pool_kernel(const float* __restrict__ x,
                                                   const float* __restrict__ alpha) {
    __shared__ float a_sm[Nv];
    __shared__ float4 red4[384];
    const int tid = threadIdx.x;
    const int r   = tid / 96;          // row within block (0..3)
    const int f0  = tid % 96;          // starting float4 index in row
    const int bc  = blockIdx.x * 4 + r;

    for (int i = tid; i < Nv; i += 384) a_sm[i] = alpha[i];
    __syncthreads();

    const float4* xp4 = reinterpret_cast<const float4*>(x) + (size_t)bc * NT4;

    float4 acc = make_float4(0.f, 0.f, 0.f, 0.f);
    int i = f0 / 3;                    // node index; f = f0 + 96k -> i = f0/3 + 32k
#pragma unroll 10
    for (int f = f0; f < NT4; f += 96, i += 32) {
        const float a = a_sm[i];
        const float4 v = xp4[f];
        acc.x += a * v.x;  acc.y += a * v.y;
        acc.z += a * v.z;  acc.w += a * v.w;
    }
    red4[tid] = acc;
    __syncthreads();

    // Final reduction: 48 threads, one per (row, t).
    if (tid < 48) {
        const int r2 = tid / Tv;
        const int t  = tid % Tv;
        const int g  = t / 4;          // phase group (f0 % 3 == g contributes to t)
        const int e  = t % 4;          // element within float4
        float s = 0.f;
#pragma unroll
        for (int m = 0; m < 32; m++) {
            const float4 v = red4[r2 * 96 + g + 3 * m];
            s += e == 0 ? v.x : (e == 1 ? v.y : (e == 2 ? v.z : v.w));
        }
        g_k[(blockIdx.x * 4 + r2) * Tv + t] = s;
    }
}

// ---------------------------------------------------------------------------
// Stage 2: att = softmax_d(kW k^T), stored TRANSPOSED g_attT[b][d][c]
// ---------------------------------------------------------------------------
__global__ void att_kernel(const float* __restrict__ W) {
    __shared__ float k_sm[Cv * Tv];   // 12 KB
    __shared__ float W_sm[Tv * Tv];
    const int b = blockIdx.x;
    const int c = threadIdx.x;        // 0..255

    for (int i = c; i < Cv * Tv; i += Cv) k_sm[i] = g_k[b * Cv * Tv + i];
    if (c < Tv * Tv) W_sm[c] = W[c];
    __syncthreads();

    float kw[Tv];
#pragma unroll
    for (int t = 0; t < Tv; t++) {
        float s = 0.f;
#pragma unroll
        for (int ss = 0; ss < Tv; ss++) s += k_sm[c * Tv + ss] * W_sm[ss * Tv + t];
        kw[t] = s;
    }

    float m = -1e30f;
    for (int d = 0; d < Cv; d++) {
        float s = 0.f;
#pragma unroll
        for (int t = 0; t < Tv; t++) s += kw[t] * k_sm[d * Tv + t];
        m = fmaxf(m, s);
    }

    float* attT = g_attT + (size_t)b * Cv * Cv;   // [d][c]
    float Z = 0.f;
    for (int d = 0; d < Cv; d++) {
        float s = 0.f;
#pragma unroll
        for (int t = 0; t < Tv; t++) s += kw[t] * k_sm[d * Tv + t];
        float e = expf(s - m);
        attT[d * Cv + c] = e;
        Z += e;
    }

    const float inv = 1.f / Z;
    for (int d = 0; d < Cv; d++) attT[d * Cv + c] *= inv;
}

// ---------------------------------------------------------------------------
// Stage 3: out[b] = att[b] (256x256) @ x[b] (256x3684)
// BM=BN=128, BK=16, 8x8 microtile on FFMA2 (f32x2), 256 threads.
// A tile stored PRE-DUPLICATED in smem ((a,a) pairs) -> zero mov.b64 packs in
// the inner loop; 4 LDS.128 deliver 8 packed A pairs (2-address broadcast per
// warp, conflict-free). Double-buffered, one __syncthreads per k-tile.
// ---------------------------------------------------------------------------
#define BM 128
#define BN 128
#define BK 16
#define TM 8
#define TN 8
#define NITER (Cv / BK)   // 16

__global__ __launch_bounds__(256, 2) void mix_kernel(const float* __restrict__ x,
                                                     float* __restrict__ out) {
    __shared__ float As2[2][BK][BM * 2];  // duplicated A: 32 KB
    __shared__ float Bs[2][BK][BN];       // 16 KB  (total 48 KB = static limit)

    const int b  = blockIdx.z;
    const int m0 = blockIdx.y * BM;
    const int n0 = blockIdx.x * BN;
    const int tid = threadIdx.x;
    const int tx = tid % 16;
    const int ty = tid / 16;

    const float* AT = g_attT + (size_t)b * Cv * Cv;  // [k=256][m=256]
    const float* Bx = x + (size_t)b * Cv * NT;       // [256][3684]
    float*       O  = out + (size_t)b * Cv * NT;

    unsigned long long acc[TM][TN / 2] = {};   // 8 rows x 4 packed pairs

    const int krow = tid / 32;          // 0..7 (+8 on 2nd pass)
    const int mcol = (tid % 32) * 4;    // 0..124
    const int gcol = n0 + mcol;         // global B column
    const bool bok = (gcol < NT);       // NT % 4 == 0: float4 predication safe

    // ---- prologue: tile 0 into buffer 0 (A duplicated at store time) ----
#pragma unroll
    for (int p = 0; p < 2; p++) {
        int kk = krow + p * 8;
        float4 a = *reinterpret_cast<const float4*>(AT + (size_t)kk * Cv + m0 + mcol);
        *reinterpret_cast<float4*>(&As2[0][kk][2 * mcol]) =
            make_float4(a.x, a.x, a.y, a.y);
        *reinterpret_cast<float4*>(&As2[0][kk][2 * mcol + 4]) =
            make_float4(a.z, a.z, a.w, a.w);
        float4 v = make_float4(0.f, 0.f, 0.f, 0.f);
        if (bok) v = *reinterpret_cast<const float4*>(Bx + (size_t)kk * NT + gcol);
        *reinterpret_cast<float4*>(&Bs[0][kk][mcol]) = v;
    }
    __syncthreads();

#pragma unroll 1
    for (int it = 0; it < NITER; it++) {
        const int cur = it & 1;

        // ---- issue next tile's global loads (latency hidden by compute) ----
        float4 a_st[2], b_st[2];
        const bool has_next = (it + 1 < NITER);
        if (has_next) {
            const int k0n = (it + 1) * BK;
#pragma unroll
            for (int p = 0; p < 2; p++) {
                int kk = k0n + krow + p * 8;
                a_st[p] = *reinterpret_cast<const float4*>(AT + (size_t)kk * Cv + m0 + mcol);
                float4 v = make_float4(0.f, 0.f, 0.f, 0.f);
                if (bok) v = *reinterpret_cast<const float4*>(Bx + (size_t)kk * NT + gcol);
                b_st[p] = v;
            }
        }

        // ---- compute on buffer `cur` ----
#pragma unroll
        for (int k = 0; k < BK; k++) {
            const ulonglong2 rb01 =
                *reinterpret_cast<const ulonglong2*>(&Bs[cur][k][tx * TN]);
            const ulonglong2 rb23 =
                *reinterpret_cast<const ulonglong2*>(&Bs[cur][k][tx * TN + 4]);
            unsigned long long rb[TN / 2] = {rb01.x, rb01.y, rb23.x, rb23.y};

            // 4 LDS.128 -> 8 duplicated A pairs (no mov.b64 packing)
            const ulonglong2* ap =
                reinterpret_cast<const ulonglong2*>(&As2[cur][k][2 * ty * TM]);
            const ulonglong2 ra01 = ap[0];
            const ulonglong2 ra23 = ap[1];
            const ulonglong2 ra45 = ap[2];
            const ulonglong2 ra67 = ap[3];
            const unsigned long long ra[TM] = {ra01.x, ra01.y, ra23.x, ra23.y,
                                               ra45.x, ra45.y, ra67.x, ra67.y};
#pragma unroll
            for (int i = 0; i < TM; i++)
#pragma unroll
                for (int j = 0; j < TN / 2; j++)
                    fma_f32x2(acc[i][j], ra[i], rb[j]);
        }

        // ---- stage next tile into the other buffer, one sync ----
        if (has_next) {
            const int nxt = cur ^ 1;
#pragma unroll
            for (int p = 0; p < 2; p++) {
                int kk = krow + p * 8;
                float4 a = a_st[p];
                *reinterpret_cast<float4*>(&As2[nxt][kk][2 * mcol]) =
                    make_float4(a.x, a.x, a.y, a.y);
                *reinterpret_cast<float4*>(&As2[nxt][kk][2 * mcol + 4]) =
                    make_float4(a.z, a.z, a.w, a.w);
                *reinterpret_cast<float4*>(&Bs[nxt][kk][mcol]) = b_st[p];
            }
            __syncthreads();
        }
    }

    // ---- epilogue: 8x8 per thread; per-float4 column predication ----
#pragma unroll
    for (int i = 0; i < TM; i++) {
        int row = m0 + ty * TM + i;
#pragma unroll
        for (int j4 = 0; j4 < 2; j4++) {
            int col = n0 + tx * TN + j4 * 4;
            if (col < NT) {
                float v0, v1, v2, v3;
                unpack_f32x2(acc[i][j4 * 2 + 0], v0, v1);
                unpack_f32x2(acc[i][j4 * 2 + 1], v2, v3);
                *reinterpret_cast<float4*>(O + (size_t)row * NT + col) =
                    make_float4(v0, v1, v2, v3);
            }
        }
    }
}

// ---------------------------------------------------------------------------
extern "C" void kernel_launch(void* const* d_in, const int* in_sizes, int n_in,
                              void* d_out, int out_size) {
    const float* x     = (const float*)d_in[0];  // [64,256,307,12]
    const float* W     = (const float*)d_in[1];  // [12,12]
    const float* alpha = (const float*)d_in[2];  // [307]
    float*       out   = (float*)d_out;          // [64,256,307,12]

    pool_kernel<<<Bv * Cv / 4, 384>>>(x, alpha);
    att_kernel<<<Bv, Cv>>>(W);

    dim3 grid((NT + BN - 1) / BN, Cv / BM, Bv);  // (29, 2, 64)
    mix_kernel<<<grid, 256>>>(x, out);
}

// round 12
// speedup vs baseline: 2.1142x; 2.1142x over previous
#include <cuda_runtime.h>
#include <cuda_bf16.h>
#include <cstdint>

// Problem constants
#define Bv 64
#define Cv 256
#define Nv 307
#define Tv 12
#define NT (Nv * Tv)     // 3684
#define NT4 (NT / 4)     // 921

// Scratch (device globals: allocation-free rule)
__device__ float g_k[Bv * Cv * Tv];             // pooled k: [B, C, T]
__device__ float g_attT[(size_t)Bv * Cv * Cv];  // softmax(att) TRANSPOSED: [b][k][m]

// ---------------------------------------------------------------------------
// helpers
// ---------------------------------------------------------------------------
__device__ __forceinline__ uint32_t smem_u32(const void* p) {
    uint32_t a;
    asm("{ .reg .u64 t; cvta.to.shared.u64 t, %1; cvt.u32.u64 %0, t; }" : "=r"(a) : "l"(p));
    return a;
}
// pack two floats as bf16x2 (low half = first arg)
__device__ __forceinline__ uint32_t bpack(float f0, float f1) {
    unsigned short u0 = __bfloat16_as_ushort(__float2bfloat16(f0));
    unsigned short u1 = __bfloat16_as_ushort(__float2bfloat16(f1));
    return (uint32_t)u0 | ((uint32_t)u1 << 16);
}
__device__ __forceinline__ float bres(float f) {   // residual after bf16 truncation
    return f - __bfloat162float(__float2bfloat16(f));
}
__device__ __forceinline__ void ldsm_x4_t(uint32_t& r0, uint32_t& r1, uint32_t& r2,
                                          uint32_t& r3, uint32_t addr) {
    asm volatile("ldmatrix.sync.aligned.m8n8.x4.trans.shared.b16 {%0,%1,%2,%3}, [%4];"
                 : "=r"(r0), "=r"(r1), "=r"(r2), "=r"(r3) : "r"(addr));
}
__device__ __forceinline__ void ldsm_x2_t(uint32_t& r0, uint32_t& r1, uint32_t addr) {
    asm volatile("ldmatrix.sync.aligned.m8n8.x2.trans.shared.b16 {%0,%1}, [%2];"
                 : "=r"(r0), "=r"(r1) : "r"(addr));
}
__device__ __forceinline__ void mma_bf16(float* c, uint32_t a0, uint32_t a1, uint32_t a2,
                                         uint32_t a3, uint32_t b0, uint32_t b1) {
    asm volatile(
        "mma.sync.aligned.m16n8k16.row.col.f32.bf16.bf16.f32 "
        "{%0,%1,%2,%3}, {%4,%5,%6,%7}, {%8,%9}, {%0,%1,%2,%3};"
        : "+f"(c[0]), "+f"(c[1]), "+f"(c[2]), "+f"(c[3])
        : "r"(a0), "r"(a1), "r"(a2), "r"(a3), "r"(b0), "r"(b1));
}

// ---------------------------------------------------------------------------
// Stage 1 (v3): pooling
// ---------------------------------------------------------------------------
__global__ __launch_bounds__(384) void pool_kernel(const float* __restrict__ x,
                                                   const float* __restrict__ alpha) {
    __shared__ float a_sm[Nv];
    __shared__ float4 red4[384];
    const int tid = threadIdx.x;
    const int r   = tid / 96;
    const int f0  = tid % 96;
    const int bc  = blockIdx.x * 4 + r;

    for (int i = tid; i < Nv; i += 384) a_sm[i] = alpha[i];
    __syncthreads();

    const float4* xp4 = reinterpret_cast<const float4*>(x) + (size_t)bc * NT4;
    const int i0 = f0 / 3;

    float4 acc = make_float4(0.f, 0.f, 0.f, 0.f);
    {
        float4 vv[5]; float aa[5];
#pragma unroll
        for (int u = 0; u < 5; u++) vv[u] = xp4[f0 + u * 96];
#pragma unroll
        for (int u = 0; u < 5; u++) aa[u] = a_sm[i0 + u * 32];
#pragma unroll
        for (int u = 0; u < 5; u++) {
            acc.x += aa[u] * vv[u].x;  acc.y += aa[u] * vv[u].y;
            acc.z += aa[u] * vv[u].z;  acc.w += aa[u] * vv[u].w;
        }
    }
    {
        float4 vv[4]; float aa[4];
#pragma unroll
        for (int u = 0; u < 4; u++) vv[u] = xp4[f0 + (5 + u) * 96];
#pragma unroll
        for (int u = 0; u < 4; u++) aa[u] = a_sm[i0 + (5 + u) * 32];
#pragma unroll
        for (int u = 0; u < 4; u++) {
            acc.x += aa[u] * vv[u].x;  acc.y += aa[u] * vv[u].y;
            acc.z += aa[u] * vv[u].z;  acc.w += aa[u] * vv[u].w;
        }
    }
    if (f0 + 9 * 96 < NT4) {
        const float a = a_sm[i0 + 9 * 32];
        const float4 v = xp4[f0 + 9 * 96];
        acc.x += a * v.x;  acc.y += a * v.y;
        acc.z += a * v.z;  acc.w += a * v.w;
    }

    red4[tid] = acc;
    __syncthreads();

    if (tid < 48) {
        const int r2 = tid / Tv;
        const int t  = tid % Tv;
        const int g  = t / 4;
        const int e  = t % 4;
        float s = 0.f;
#pragma unroll
        for (int m = 0; m < 32; m++) {
            const float4 v = red4[r2 * 96 + g + 3 * m];
            s += e == 0 ? v.x : (e == 1 ? v.y : (e == 2 ? v.z : v.w));
        }
        g_k[(blockIdx.x * 4 + r2) * Tv + t] = s;
    }
}

// ---------------------------------------------------------------------------
// Stage 2: att = softmax_d(kW k^T), stored TRANSPOSED g_attT[b][d][c]
// ---------------------------------------------------------------------------
__global__ void att_kernel(const float* __restrict__ W) {
    __shared__ float k_sm[Cv * Tv];
    __shared__ float W_sm[Tv * Tv];
    const int b = blockIdx.x;
    const int c = threadIdx.x;

    for (int i = c; i < Cv * Tv; i += Cv) k_sm[i] = g_k[b * Cv * Tv + i];
    if (c < Tv * Tv) W_sm[c] = W[c];
    __syncthreads();

    float kw[Tv];
#pragma unroll
    for (int t = 0; t < Tv; t++) {
        float s = 0.f;
#pragma unroll
        for (int ss = 0; ss < Tv; ss++) s += k_sm[c * Tv + ss] * W_sm[ss * Tv + t];
        kw[t] = s;
    }

    float m = -1e30f;
    for (int d = 0; d < Cv; d++) {
        float s = 0.f;
#pragma unroll
        for (int t = 0; t < Tv; t++) s += kw[t] * k_sm[d * Tv + t];
        m = fmaxf(m, s);
    }

    float* attT = g_attT + (size_t)b * Cv * Cv;
    float Z = 0.f;
    for (int d = 0; d < Cv; d++) {
        float s = 0.f;
#pragma unroll
        for (int t = 0; t < Tv; t++) s += kw[t] * k_sm[d * Tv + t];
        float e = expf(s - m);
        attT[d * Cv + c] = e;
        Z += e;
    }

    const float inv = 1.f / Z;
    for (int d = 0; d < Cv; d++) attT[d * Cv + c] *= inv;
}

// ---------------------------------------------------------------------------
// Stage 3 (mma.sync bf16 hi/lo split): out[b] = att[b] @ x[b]
// CTA: 128m x 64n x 32k, 256 thr, 8 warps (4m x 2n), warp tile 32x32.
// A smem [k][m] (pitch 272B), B smem [k][n] (pitch 144B) -> ldmatrix .trans
// fragments, conflict-free (row stride = 4 banks mod 32).
// 3-term split: D += Ah*Bh + Ah*Bl + Al*Bh (al*bl dropped, ~2^-18).
// ---------------------------------------------------------------------------
#define BMm 128
#define BNm 64
#define BKm 32
#define KSTEPS (Cv / BKm)   // 8
#define APITCH 272          // 128 bf16 + 8 pad
#define BPITCH 144          // 64 bf16 + 8 pad

__global__ __launch_bounds__(256) void mix_mma_kernel(const float* __restrict__ x,
                                                      float* __restrict__ out) {
    __shared__ __align__(16) unsigned char Ah[BKm * APITCH];
    __shared__ __align__(16) unsigned char Al[BKm * APITCH];
    __shared__ __align__(16) unsigned char Bh[BKm * BPITCH];
    __shared__ __align__(16) unsigned char Bl[BKm * BPITCH];

    const int tid  = threadIdx.x;
    const int wid  = tid >> 5;
    const int lane = tid & 31;
    const int b    = blockIdx.z;
    const int m0g  = blockIdx.y * BMm;
    const int n0g  = blockIdx.x * BNm;
    const int m_w  = (wid & 3) * 32;   // warp m offset (4 m-warps)
    const int n_w  = (wid >> 2) * 32;  // warp n offset (2 n-warps)

    const float* AT = g_attT + (size_t)b * Cv * Cv;  // [k=256][m=256]
    const float* Bx = x + (size_t)b * Cv * NT;       // [k=256][n=3684]
    float*       O  = out + (size_t)b * Cv * NT;

    const uint32_t sAh = smem_u32(Ah), sAl = smem_u32(Al);
    const uint32_t sBh = smem_u32(Bh), sBl = smem_u32(Bl);

    float acc[2][4][4] = {};   // [msub][nsub][frag]

    // staging registers
    float4 aS[4], bS[2];

    // A loader: pass p -> k = p*8+wid, m = lane*4
    // B loader: pass p -> k = p*16 + (tid>>4), n = (lane&15)*4
    const int akl = wid;            // + p*8
    const int aml = lane * 4;
    const int bkl = tid >> 4;       // + p*16
    const int bnl = (lane & 15) * 4;

    // ---- prologue: load tile 0 ----
#pragma unroll
    for (int p = 0; p < 4; p++)
        aS[p] = *reinterpret_cast<const float4*>(AT + (size_t)(p * 8 + akl) * Cv + m0g + aml);
#pragma unroll
    for (int p = 0; p < 2; p++) {
        const int gn = n0g + bnl;
        float4 v = make_float4(0.f, 0.f, 0.f, 0.f);
        if (gn < NT)
            v = *reinterpret_cast<const float4*>(Bx + (size_t)(p * 16 + bkl) * NT + gn);
        bS[p] = v;
    }

#pragma unroll 1
    for (int it = 0; it < KSTEPS; it++) {
        if (it) __syncthreads();   // all warps finished MMA on previous tile

        // ---- STS: convert fp32 -> bf16 hi/lo ----
#pragma unroll
        for (int p = 0; p < 4; p++) {
            const float4 v = aS[p];
            const int off = (p * 8 + akl) * APITCH + aml * 2;
            *reinterpret_cast<uint2*>(Ah + off) =
                make_uint2(bpack(v.x, v.y), bpack(v.z, v.w));
            *reinterpret_cast<uint2*>(Al + off) =
                make_uint2(bpack(bres(v.x), bres(v.y)), bpack(bres(v.z), bres(v.w)));
        }
#pragma unroll
        for (int p = 0; p < 2; p++) {
            const float4 v = bS[p];
            const int off = (p * 16 + bkl) * BPITCH + bnl * 2;
            *reinterpret_cast<uint2*>(Bh + off) =
                make_uint2(bpack(v.x, v.y), bpack(v.z, v.w));
            *reinterpret_cast<uint2*>(Bl + off) =
                make_uint2(bpack(bres(v.x), bres(v.y)), bpack(bres(v.z), bres(v.w)));
        }
        __syncthreads();

        // ---- prefetch next tile (overlaps MMA below) ----
        if (it + 1 < KSTEPS) {
            const int k0 = (it + 1) * BKm;
#pragma unroll
            for (int p = 0; p < 4; p++)
                aS[p] = *reinterpret_cast<const float4*>(
                    AT + (size_t)(k0 + p * 8 + akl) * Cv + m0g + aml);
#pragma unroll
            for (int p = 0; p < 2; p++) {
                const int gn = n0g + bnl;
                float4 v = make_float4(0.f, 0.f, 0.f, 0.f);
                if (gn < NT)
                    v = *reinterpret_cast<const float4*>(
                        Bx + (size_t)(k0 + p * 16 + bkl) * NT + gn);
                bS[p] = v;
            }
        }

        // ---- MMA over this tile: 2 k16 steps ----
#pragma unroll
        for (int ks = 0; ks < 2; ks++) {
            // A fragment addresses (ldmatrix.x4.trans from k-major [k][m]):
            // lanes 0-7:(k0-7,m), 8-15:(k0-7,m+8), 16-23:(k8-15,m), 24-31:(k8-15,m+8)
            const int kk = ks * 16 + (lane & 7) + ((lane & 16) >> 1);
            uint32_t ah[2][4], al[2][4];
#pragma unroll
            for (int ms = 0; ms < 2; ms++) {
                const int mm = m_w + ms * 16 + (lane & 8);
                const uint32_t o = (uint32_t)(kk * APITCH + mm * 2);
                ldsm_x4_t(ah[ms][0], ah[ms][1], ah[ms][2], ah[ms][3], sAh + o);
                ldsm_x4_t(al[ms][0], al[ms][1], al[ms][2], al[ms][3], sAl + o);
            }
            // B fragments (ldmatrix.x2.trans): lanes 0-7:(k0-7,n), 8-15:(k8-15,n)
            const int bkk = ks * 16 + (lane & 15);
            uint32_t bh[4][2], bl[4][2];
#pragma unroll
            for (int ns = 0; ns < 4; ns++) {
                const uint32_t o = (uint32_t)(bkk * BPITCH + (n_w + ns * 8) * 2);
                ldsm_x2_t(bh[ns][0], bh[ns][1], sBh + o);
                ldsm_x2_t(bl[ns][0], bl[ns][1], sBl + o);
            }
#pragma unroll
            for (int ms = 0; ms < 2; ms++)
#pragma unroll
                for (int ns = 0; ns < 4; ns++) {
                    mma_bf16(acc[ms][ns], ah[ms][0], ah[ms][1], ah[ms][2], ah[ms][3],
                             bh[ns][0], bh[ns][1]);
                    mma_bf16(acc[ms][ns], ah[ms][0], ah[ms][1], ah[ms][2], ah[ms][3],
                             bl[ns][0], bl[ns][1]);
                    mma_bf16(acc[ms][ns], al[ms][0], al[ms][1], al[ms][2], al[ms][3],
                             bh[ns][0], bh[ns][1]);
                }
        }
    }

    // ---- epilogue ----
    // c0,c1: (row = lane/4, col = (lane%4)*2 + {0,1}); c2,c3: row+8
#pragma unroll
    for (int ms = 0; ms < 2; ms++)
#pragma unroll
        for (int ns = 0; ns < 4; ns++) {
            const int row = m0g + m_w + ms * 16 + (lane >> 2);
            const int col = n0g + n_w + ns * 8 + (lane & 3) * 2;
            if (col < NT) {
                float2 v0 = make_float2(acc[ms][ns][0], acc[ms][ns][1]);
                float2 v1 = make_float2(acc[ms][ns][2], acc[ms][ns][3]);
                *reinterpret_cast<float2*>(O + (size_t)row * NT + col) = v0;
                *reinterpret_cast<float2*>(O + (size_t)(row + 8) * NT + col) = v1;
            }
        }
}

// ---------------------------------------------------------------------------
extern "C" void kernel_launch(void* const* d_in, const int* in_sizes, int n_in,
                              void* d_out, int out_size) {
    const float* x     = (const float*)d_in[0];  // [64,256,307,12]
    const float* W     = (const float*)d_in[1];  // [12,12]
    const float* alpha = (const float*)d_in[2];  // [307]
    float*       out   = (float*)d_out;          // [64,256,307,12]

    pool_kernel<<<Bv * Cv / 4, 384>>>(x, alpha);
    att_kernel<<<Bv, Cv>>>(W);

    dim3 grid((NT + BNm - 1) / BNm, Cv / BMm, Bv);  // (58, 2, 64)
    mix_mma_kernel<<<grid, 256>>>(x, out);
}